// round 12
// baseline (speedup 1.0000x reference)
#include <cuda_runtime.h>
#include <cuda_bf16.h>
#include <cstdint>
#include <stdint.h>
#include <math.h>

#define D_DIM 1024
#define B_DIM 8
#define T_DIM 1024
#define L_CH 8
#define DD (1024*1024)
#define SPECTRAL_RADIUS 0.999f
#define EPS_F 1e-8f

// GEMM tiling: CTA tile 64(M) x 128(N), K-chunk 32, 4-stage pipeline.
#define MT 64
#define NT 128
#define KC 32
#define RB 80                               // smem row bytes (40 bf16, pad 8)
#define A_BYTES (MT * RB)                   // 5120
#define B_BYTES (NT * RB)                   // 10240
#define STAGE_BYTES (2 * A_BYTES + 2 * B_BYTES)  // 30720
#define NSTAGE 4
#define GEMM_SMEM (NSTAGE * STAGE_BYTES)    // 122880

// ------------------------- device scratch ------------------------------------
__device__ float g_p[6][D_DIM];
__device__ float g_scale;
__device__ __align__(256) __nv_bfloat16 g_Wh[DD], g_Wl[DD], g_WTh[DD], g_WTl[DD];
__device__ __align__(256) __nv_bfloat16 g_Ph[DD], g_Pl[DD], g_PTh[DD], g_PTl[DD];
__device__ __align__(256) __nv_bfloat16 g_Ah[DD], g_Al[DD];      // split pair 0
__device__ __align__(256) __nv_bfloat16 g_Ch[DD], g_Cl[DD];      // split pair 1
__device__ __align__(256) float g_pow[DD], g_S[2][DD];

// ------------------------- PTX helpers ---------------------------------------
__device__ __forceinline__ unsigned smem_u32(const void* p) {
    unsigned a;
    asm("{ .reg .u64 t; cvta.to.shared.u64 t, %1; cvt.u32.u64 %0, t; }" : "=r"(a) : "l"(p));
    return a;
}
__device__ __forceinline__ void cp16(unsigned sa, const void* g) {
    asm volatile("cp.async.cg.shared.global [%0], [%1], 16;" :: "r"(sa), "l"(g));
}
__device__ __forceinline__ void cp16z(unsigned sa, const void* g, int srcsize) {
    asm volatile("cp.async.cg.shared.global [%0], [%1], 16, %2;"
                 :: "r"(sa), "l"(g), "r"(srcsize));
}
__device__ __forceinline__ void cp_commit() { asm volatile("cp.async.commit_group;"); }
__device__ __forceinline__ void cp_wait0()  { asm volatile("cp.async.wait_group 0;" ::: "memory"); }
__device__ __forceinline__ void cp_wait1()  { asm volatile("cp.async.wait_group 1;" ::: "memory"); }
__device__ __forceinline__ void cp_wait2()  { asm volatile("cp.async.wait_group 2;" ::: "memory"); }

__device__ __forceinline__ void ldsm4(unsigned addr, unsigned* r) {
    asm volatile("ldmatrix.sync.aligned.m8n8.x4.shared.b16 {%0,%1,%2,%3}, [%4];"
                 : "=r"(r[0]), "=r"(r[1]), "=r"(r[2]), "=r"(r[3]) : "r"(addr));
}
__device__ __forceinline__ void mma16816(float* c, const unsigned* a,
                                         unsigned b0, unsigned b1) {
    asm volatile(
        "mma.sync.aligned.m16n8k16.row.col.f32.bf16.bf16.f32 "
        "{%0,%1,%2,%3}, {%4,%5,%6,%7}, {%8,%9}, {%0,%1,%2,%3};"
        : "+f"(c[0]), "+f"(c[1]), "+f"(c[2]), "+f"(c[3])
        : "r"(a[0]), "r"(a[1]), "r"(a[2]), "r"(a[3]), "r"(b0), "r"(b1));
}

// ------------------------- power iteration ------------------------------------
__global__ void mv_T_kernel(const float* __restrict__ W, const float* __restrict__ vin,
                            float* __restrict__ vout) {
    int dl = threadIdx.x >> 5, lane = threadIdx.x & 31;
    int d = blockIdx.x * 8 + dl;
    float acc = 0.f;
    for (int e = lane; e < D_DIM; e += 32)
        acc += W[(size_t)e * D_DIM + d] * vin[e];
    #pragma unroll
    for (int off = 16; off; off >>= 1) acc += __shfl_down_sync(0xffffffffu, acc, off);
    if (lane == 0) vout[d] = acc;
}
__global__ void mv_N_kernel(const float* __restrict__ W, const float* __restrict__ vin,
                            float* __restrict__ vout) {
    int el = threadIdx.x >> 5, lane = threadIdx.x & 31;
    int e = blockIdx.x * 8 + el;
    float acc = 0.f;
    const float* row = W + (size_t)e * D_DIM;
    for (int d = lane; d < D_DIM; d += 32) acc += row[d] * vin[d];
    #pragma unroll
    for (int off = 16; off; off >>= 1) acc += __shfl_down_sync(0xffffffffu, acc, off);
    if (lane == 0) vout[e] = acc;
}
__global__ void finalize_kernel() {
    __shared__ float red[256];
    __shared__ float ssq[6];
    int tid = threadIdx.x;
    for (int v = 0; v < 6; v++) {
        float local = 0.f;
        for (int i = tid; i < D_DIM; i += 256) { float x = g_p[v][i]; local += x * x; }
        red[tid] = local;
        __syncthreads();
        for (int s = 128; s; s >>= 1) { if (tid < s) red[tid] += red[tid + s]; __syncthreads(); }
        if (tid == 0) ssq[v] = red[0];
        __syncthreads();
    }
    if (tid == 0) {
        float a1 = 1.f / (sqrtf(ssq[0]) + EPS_F);
        float b1 = a1 / (a1 * sqrtf(ssq[1]) + EPS_F);
        float a2 = b1 / (b1 * sqrtf(ssq[2]) + EPS_F);
        float b2 = a2 / (a2 * sqrtf(ssq[3]) + EPS_F);
        float a3 = b2 / (b2 * sqrtf(ssq[4]) + EPS_F);
        float b3 = a3 / (a3 * sqrtf(ssq[5]) + EPS_F);
        float sigma = fabsf(a3 * b3 * ssq[5]);
        g_scale = SPECTRAL_RADIUS / (sigma + EPS_F);
    }
}

// --------------------- split (+ transpose) kernel -----------------------------
__global__ void split_tr_kernel(const float* __restrict__ in, int useScale,
                                __nv_bfloat16* __restrict__ oh, __nv_bfloat16* __restrict__ ol,
                                __nv_bfloat16* __restrict__ oth, __nv_bfloat16* __restrict__ otl) {
    __shared__ float tile[32][33];
    float s = useScale ? g_scale : 1.0f;
    int bx = blockIdx.x, by = blockIdx.y;
    int tx = threadIdx.x, ty = threadIdx.y;     // 32 x 8
    #pragma unroll
    for (int k = 0; k < 4; k++) {
        int r = by * 32 + ty + k * 8, c = bx * 32 + tx;
        float v = in[(size_t)r * D_DIM + c] * s;
        tile[ty + k * 8][tx] = v;
        __nv_bfloat16 h = __float2bfloat16(v);
        oh[(size_t)r * D_DIM + c] = h;
        ol[(size_t)r * D_DIM + c] = __float2bfloat16(v - __bfloat162float(h));
    }
    __syncthreads();
    #pragma unroll
    for (int k = 0; k < 4; k++) {
        int rt = bx * 32 + ty + k * 8, ct = by * 32 + tx;
        float v = tile[tx][ty + k * 8];
        __nv_bfloat16 h = __float2bfloat16(v);
        oth[(size_t)rt * D_DIM + ct] = h;
        otl[(size_t)rt * D_DIM + ct] = __float2bfloat16(v - __bfloat162float(h));
    }
}

// ------------------------- prep for phase-1 j=0 -------------------------------
__global__ void prep1_kernel(const float* __restrict__ x, const float* __restrict__ h0,
                             __nv_bfloat16* __restrict__ ah, __nv_bfloat16* __restrict__ al) {
    size_t gid = (size_t)blockIdx.x * 256 + threadIdx.x;
    int m = (int)(gid >> 10), d = (int)(gid & 1023);
    int c = m >> 3, b = m & 7;
    int t = c * L_CH;
    float v = x[((size_t)t * B_DIM + b) * D_DIM + d];
    if (c == 0) v += h0[(size_t)b * D_DIM + d];
    __nv_bfloat16 h = __float2bfloat16(v);
    ah[gid] = h;
    al[gid] = __float2bfloat16(v - __bfloat162float(h));
}

// ------------------------- mma.sync split-bf16 GEMM ---------------------------
// R[m,n] = sum_k A[m+ashift,k]*B[n,k], A = Ah+Al, B = Bh+Bl (3-term split);
// rows with m+ashift < 0 are zero (cp.async zero-fill).
// Epilogue modes:
//  0: out[m,n] (+addsrc) ; optional split(v) -> sh/sl
//  1: phase1: v += bias; out_h[slot] = v; split(v + x[t+1]); optional fdst=S0
//  2: phase3: out_h[slot] += v; silu(h) -> fdst(out_silu); optional split(v)
__device__ __forceinline__ void load_chunk(unsigned smb, int stage,
        const __nv_bfloat16* Ah, const __nv_bfloat16* Al, int ashift,
        const __nv_bfloat16* Bh, const __nv_bfloat16* Bl,
        int arow0, int brow0, int kc, int tid) {
    unsigned sb = smb + stage * STAGE_BYTES;
    #pragma unroll
    for (int i = 0; i < 2; i++) {           // A: Ah,Al 64 rows x 4 x 16B
        int e = tid + i * 256;
        int arr = e >> 8;
        int rr = (e & 255) >> 2;
        int cc = e & 3;
        const __nv_bfloat16* src = arr ? Al : Ah;
        int r = arow0 + rr + ashift;
        int sz = (r >= 0) ? 16 : 0;
        if (r < 0) r = 0;
        cp16z(sb + arr * A_BYTES + rr * RB + cc * 16,
              src + (size_t)r * D_DIM + kc * KC + cc * 8, sz);
    }
    #pragma unroll
    for (int i = 0; i < 4; i++) {           // B: Bh,Bl 128 rows x 4 x 16B
        int e = tid + i * 256;
        int arr = e >> 9;
        int rr = (e & 511) >> 2;
        int cc = e & 3;
        const __nv_bfloat16* src = arr ? Bl : Bh;
        cp16(sb + 2 * A_BYTES + arr * B_BYTES + rr * RB + cc * 16,
             src + (size_t)(brow0 + rr) * D_DIM + kc * KC + cc * 8);
    }
    cp_commit();
}

__global__ void __launch_bounds__(256, 1)
gemm_kernel(const __nv_bfloat16* __restrict__ Ah, const __nv_bfloat16* __restrict__ Al,
            int ashift,
            const __nv_bfloat16* __restrict__ Bh, const __nv_bfloat16* __restrict__ Bl,
            float* __restrict__ out, const float* __restrict__ addsrc,
            const float* __restrict__ bias, const float* __restrict__ xnext,
            __nv_bfloat16* __restrict__ sh, __nv_bfloat16* __restrict__ sl,
            float* __restrict__ fdst, int emode, int jstep) {
    extern __shared__ char sm[];
    unsigned smb = smem_u32(sm);
    const int tid = threadIdx.x;
    const int wid = tid >> 5, lane = tid & 31;
    const int bx = blockIdx.x, by = blockIdx.y;
    const int warp_m = wid >> 2, warp_n = wid & 3;
    const int g = lane >> 2, tg = lane & 3;

    int arow0 = by * MT, brow0 = bx * NT;

    unsigned lrow = lane & 15, lhalf = lane >> 4;
    unsigned aBase = smb + (warp_m * 32 + lrow) * RB + lhalf * 16;
    unsigned bBase = smb + 2 * A_BYTES + (warp_n * 32 + lrow) * RB + lhalf * 16;

    float acc[2][4][4];
    #pragma unroll
    for (int i = 0; i < 2; i++)
        #pragma unroll
        for (int j = 0; j < 4; j++)
            #pragma unroll
            for (int q = 0; q < 4; q++) acc[i][j][q] = 0.f;

    const int NKC = D_DIM / KC;   // 32
    // prologue: 3 chunks in flight
    #pragma unroll
    for (int s = 0; s < NSTAGE - 1; s++)
        load_chunk(smb, s, Ah, Al, ashift, Bh, Bl, arow0, brow0, s, tid);

    for (int kc = 0; kc < NKC; kc++) {
        int st = kc & (NSTAGE - 1);
        int remain = NKC - 1 - kc;
        if (remain >= 2) cp_wait2();
        else if (remain == 1) cp_wait1();
        else cp_wait0();
        __syncthreads();
        if (kc + NSTAGE - 1 < NKC)
            load_chunk(smb, (kc + NSTAGE - 1) & (NSTAGE - 1),
                       Ah, Al, ashift, Bh, Bl, arow0, brow0, kc + NSTAGE - 1, tid);

        unsigned sa = aBase + st * STAGE_BYTES;
        unsigned sb = bBase + st * STAGE_BYTES;
        #pragma unroll
        for (int ks = 0; ks < 2; ks++) {
            unsigned ko = ks * 32;
            unsigned AH0[4], AH1[4], AL0[4], AL1[4];
            ldsm4(sa + ko, AH0);
            ldsm4(sa + 16 * RB + ko, AH1);
            ldsm4(sa + A_BYTES + ko, AL0);
            ldsm4(sa + A_BYTES + 16 * RB + ko, AL1);
            unsigned BH0[4], BH1[4], BL0[4], BL1[4];
            ldsm4(sb + ko, BH0);
            ldsm4(sb + 16 * RB + ko, BH1);
            ldsm4(sb + B_BYTES + ko, BL0);
            ldsm4(sb + B_BYTES + 16 * RB + ko, BL1);

            unsigned bh[4][2] = {{BH0[0],BH0[2]},{BH0[1],BH0[3]},
                                 {BH1[0],BH1[2]},{BH1[1],BH1[3]}};
            unsigned bl[4][2] = {{BL0[0],BL0[2]},{BL0[1],BL0[3]},
                                 {BL1[0],BL1[2]},{BL1[1],BL1[3]}};
            #pragma unroll
            for (int j = 0; j < 4; j++) {
                mma16816(acc[0][j], AH0, bh[j][0], bh[j][1]);
                mma16816(acc[0][j], AH0, bl[j][0], bl[j][1]);
                mma16816(acc[0][j], AL0, bh[j][0], bh[j][1]);
                mma16816(acc[1][j], AH1, bh[j][0], bh[j][1]);
                mma16816(acc[1][j], AH1, bl[j][0], bl[j][1]);
                mma16816(acc[1][j], AL1, bh[j][0], bh[j][1]);
            }
        }
    }

    // Epilogue
    #pragma unroll
    for (int i = 0; i < 2; i++) {
        #pragma unroll
        for (int j = 0; j < 4; j++) {
            int rm = by * MT + warp_m * 32 + i * 16 + g;
            int col = bx * NT + warp_n * 32 + j * 8 + tg * 2;
            #pragma unroll
            for (int half = 0; half < 2; half++) {
                int r = rm + half * 8;
                float vx = acc[i][j][half * 2 + 0];
                float vy = acc[i][j][half * 2 + 1];
                size_t flat = (size_t)r * D_DIM + col;
                if (emode == 0) {
                    if (addsrc) {
                        float2 a2 = *(const float2*)(addsrc + flat);
                        vx += a2.x; vy += a2.y;
                    }
                    float2 o; o.x = vx; o.y = vy;
                    *(float2*)(out + flat) = o;
                    if (sh) {
                        __nv_bfloat16 hx = __float2bfloat16(vx);
                        __nv_bfloat16 hy = __float2bfloat16(vy);
                        __nv_bfloat162 h2; h2.x = hx; h2.y = hy;
                        __nv_bfloat162 l2;
                        l2.x = __float2bfloat16(vx - __bfloat162float(hx));
                        l2.y = __float2bfloat16(vy - __bfloat162float(hy));
                        *(__nv_bfloat162*)(sh + flat) = h2;
                        *(__nv_bfloat162*)(sl + flat) = l2;
                    }
                } else {
                    int c = r >> 3, b = r & 7;
                    int t1 = c * L_CH + jstep + 1;
                    size_t idx = ((size_t)t1 * B_DIM + b) * D_DIM + col;
                    if (emode == 1) {
                        float2 b2 = *(const float2*)(bias + col);
                        vx += b2.x; vy += b2.y;
                        float2 o; o.x = vx; o.y = vy;
                        *(float2*)(out + idx) = o;
                        if (fdst) { float2 f; f.x = vx; f.y = vy;
                                    *(float2*)(fdst + flat) = f; }
                        float sx = vx, sy = vy;
                        if (xnext) {
                            float2 xv = *(const float2*)(xnext + idx);
                            sx += xv.x; sy += xv.y;
                        }
                        __nv_bfloat16 hx = __float2bfloat16(sx);
                        __nv_bfloat16 hy = __float2bfloat16(sy);
                        __nv_bfloat162 h2; h2.x = hx; h2.y = hy;
                        __nv_bfloat162 l2;
                        l2.x = __float2bfloat16(sx - __bfloat162float(hx));
                        l2.y = __float2bfloat16(sy - __bfloat162float(hy));
                        *(__nv_bfloat162*)(sh + flat) = h2;
                        *(__nv_bfloat162*)(sl + flat) = l2;
                    } else {  // emode == 2: accumulate + fused silu
                        float2 o = *(const float2*)(out + idx);
                        o.x += vx; o.y += vy;
                        *(float2*)(out + idx) = o;
                        // silu of final h -> output[t1-1] (= idx - B*D)
                        float2 sv;
                        sv.x = o.x / (1.f + expf(-o.x));
                        sv.y = o.y / (1.f + expf(-o.y));
                        *(float2*)(fdst + idx - (size_t)B_DIM * D_DIM) = sv;
                        if (sh) {
                            __nv_bfloat16 hx = __float2bfloat16(vx);
                            __nv_bfloat16 hy = __float2bfloat16(vy);
                            __nv_bfloat162 h2; h2.x = hx; h2.y = hy;
                            __nv_bfloat162 l2;
                            l2.x = __float2bfloat16(vx - __bfloat162float(hx));
                            l2.y = __float2bfloat16(vy - __bfloat162float(hy));
                            *(__nv_bfloat162*)(sh + flat) = h2;
                            *(__nv_bfloat162*)(sl + flat) = l2;
                        }
                    }
                }
            }
        }
    }
}

// ------------------------------- launcher ------------------------------------
extern "C" void kernel_launch(void* const* d_in, const int* in_sizes, int n_in,
                              void* d_out, int out_size) {
    const float* x  = (const float*)d_in[0];
    const float* h0 = (const float*)d_in[1];
    const float* W  = (const float*)d_in[2];
    const float* bv = (const float*)d_in[3];
    const float* u  = (const float*)d_in[4];

    float* out_silu = (float*)d_out;
    float* out_h    = (float*)d_out + (size_t)T_DIM * B_DIM * D_DIM;  // h[0..T]

    float *p, *pow_, *S0, *S1;
    __nv_bfloat16 *Wh, *Wl, *WTh, *WTl, *Ph, *Pl, *PTh, *PTl;
    __nv_bfloat16 *p0h, *p0l, *p1h, *p1l;
    cudaGetSymbolAddress((void**)&p, g_p);
    cudaGetSymbolAddress((void**)&pow_, g_pow);
    cudaGetSymbolAddress((void**)&S0, g_S);   S1 = S0 + DD;
    cudaGetSymbolAddress((void**)&Wh, g_Wh);   cudaGetSymbolAddress((void**)&Wl, g_Wl);
    cudaGetSymbolAddress((void**)&WTh, g_WTh); cudaGetSymbolAddress((void**)&WTl, g_WTl);
    cudaGetSymbolAddress((void**)&Ph, g_Ph);   cudaGetSymbolAddress((void**)&Pl, g_Pl);
    cudaGetSymbolAddress((void**)&PTh, g_PTh); cudaGetSymbolAddress((void**)&PTl, g_PTl);
    cudaGetSymbolAddress((void**)&p0h, g_Ah);  cudaGetSymbolAddress((void**)&p0l, g_Al);
    cudaGetSymbolAddress((void**)&p1h, g_Ch);  cudaGetSymbolAddress((void**)&p1l, g_Cl);

    cudaFuncSetAttribute(gemm_kernel, cudaFuncAttributeMaxDynamicSharedMemorySize,
                         GEMM_SMEM);

    __nv_bfloat16* pairh[2] = {p0h, p1h};
    __nv_bfloat16* pairl[2] = {p0l, p1l};

    // h[0] = h0
    cudaMemcpyAsync(out_h, h0, sizeof(float) * B_DIM * D_DIM, cudaMemcpyDeviceToDevice, 0);

    // ---- spectral scale ----
    mv_T_kernel<<<128, 256>>>(W, u, p + 0 * D_DIM);
    mv_N_kernel<<<128, 256>>>(W, p + 0 * D_DIM, p + 1 * D_DIM);
    mv_T_kernel<<<128, 256>>>(W, p + 1 * D_DIM, p + 2 * D_DIM);
    mv_N_kernel<<<128, 256>>>(W, p + 2 * D_DIM, p + 3 * D_DIM);
    mv_T_kernel<<<128, 256>>>(W, p + 3 * D_DIM, p + 4 * D_DIM);
    mv_N_kernel<<<128, 256>>>(W, p + 4 * D_DIM, p + 5 * D_DIM);
    finalize_kernel<<<1, 256>>>();

    dim3 trg(32, 32), trb(32, 8);
    dim3 gg(D_DIM / NT, D_DIM / MT);   // (8, 16)
    split_tr_kernel<<<trg, trb>>>(W, 1, Wh, Wl, WTh, WTl);

    // ---- phase 1: 8 GEMMs; epilogue writes h slot + split(h + x_next) --------
    prep1_kernel<<<4096, 256>>>(x, h0, p0h, p0l);
    for (int j = 0; j < L_CH; j++) {
        int in = j & 1, outp = (j + 1) & 1;
        gemm_kernel<<<gg, 256, GEMM_SMEM>>>(
            pairh[in], pairl[in], 0, Wh, Wl, out_h, nullptr, bv,
            (j < 7) ? x : nullptr, pairh[outp], pairl[outp],
            (j == 7) ? S0 : nullptr, 1, j);
    }

    // ---- squarings to A^8 ----
    gemm_kernel<<<gg, 256, GEMM_SMEM>>>(Wh, Wl, 0, WTh, WTl, pow_, nullptr, nullptr,
                                        nullptr, nullptr, nullptr, nullptr, 0, 0);
    split_tr_kernel<<<trg, trb>>>(pow_, 0, Ph, Pl, PTh, PTl);
    gemm_kernel<<<gg, 256, GEMM_SMEM>>>(Ph, Pl, 0, PTh, PTl, pow_, nullptr, nullptr,
                                        nullptr, nullptr, nullptr, nullptr, 0, 0);
    split_tr_kernel<<<trg, trb>>>(pow_, 0, Ph, Pl, PTh, PTl);
    gemm_kernel<<<gg, 256, GEMM_SMEM>>>(Ph, Pl, 0, PTh, PTl, pow_, nullptr, nullptr,
                                        nullptr, nullptr, nullptr, nullptr, 0, 0);
    split_tr_kernel<<<trg, trb>>>(pow_, 0, Ph, Pl, PTh, PTl);

    // ---- boundary doubling scan: 7 rounds; shift folded into A-loads ---------
    float* Sc = S0;
    float* Sn = S1;
    for (int r = 0; r < 7; r++) {
        int in = r & 1, outp = (r + 1) & 1;
        gemm_kernel<<<gg, 256, GEMM_SMEM>>>(
            pairh[in], pairl[in], -(1 << r) * B_DIM, Ph, Pl, Sn, Sc, nullptr,
            nullptr, pairh[outp], pairl[outp], nullptr, 0, 0);
        float* tmp = Sc; Sc = Sn; Sn = tmp;
        if (r < 6) {
            gemm_kernel<<<gg, 256, GEMM_SMEM>>>(Ph, Pl, 0, PTh, PTl, pow_, nullptr,
                                                nullptr, nullptr, nullptr, nullptr,
                                                nullptr, 0, 0);
            split_tr_kernel<<<trg, trb>>>(pow_, 0, Ph, Pl, PTh, PTl);
        }
    }

    // ---- phase 3: fixup; epilogue accumulates into h slots + fused silu ------
    for (int j = 0; j < L_CH; j++) {
        int in = (j + 1) & 1, outp = j & 1;
        gemm_kernel<<<gg, 256, GEMM_SMEM>>>(
            pairh[in], pairl[in], (j == 0) ? -B_DIM : 0, Wh, Wl, out_h, nullptr,
            nullptr, nullptr, (j < 7) ? pairh[outp] : nullptr,
            (j < 7) ? pairl[outp] : nullptr, out_silu, 2, j);
    }
}

// round 13
// speedup vs baseline: 1.0002x; 1.0002x over previous
#include <cuda_runtime.h>
#include <cuda_bf16.h>
#include <cstdint>
#include <stdint.h>
#include <math.h>

#define D_DIM 1024
#define B_DIM 8
#define T_DIM 1024
#define L_CH 8
#define DD (1024*1024)
#define SPECTRAL_RADIUS 0.999f
#define EPS_F 1e-8f

// GEMM tiling: CTA tile 64(M) x 128(N), K-chunk 32, 4-stage pipeline.
#define MT 64
#define NT 128
#define KC 32
#define RB 80                               // smem row bytes (40 bf16, pad 8)
#define A_BYTES (MT * RB)                   // 5120
#define B_BYTES (NT * RB)                   // 10240
#define STAGE_BYTES (2 * A_BYTES + 2 * B_BYTES)  // 30720
#define NSTAGE 4
#define GEMM_SMEM (NSTAGE * STAGE_BYTES)    // 122880

// ------------------------- device scratch ------------------------------------
__device__ float g_p[6][D_DIM];
__device__ float g_scale;
__device__ __align__(256) __nv_bfloat16 g_Wh[DD], g_Wl[DD], g_WTh[DD], g_WTl[DD];
__device__ __align__(256) __nv_bfloat16 g_Ph[DD], g_Pl[DD], g_PTh[DD], g_PTl[DD];
__device__ __align__(256) __nv_bfloat16 g_Ah[DD], g_Al[DD];      // split pair 0
__device__ __align__(256) __nv_bfloat16 g_Ch[DD], g_Cl[DD];      // split pair 1
__device__ __align__(256) float g_pow[DD], g_S[2][DD];

// ------------------------- PTX helpers ---------------------------------------
__device__ __forceinline__ unsigned smem_u32(const void* p) {
    unsigned a;
    asm("{ .reg .u64 t; cvta.to.shared.u64 t, %1; cvt.u32.u64 %0, t; }" : "=r"(a) : "l"(p));
    return a;
}
__device__ __forceinline__ void cp16(unsigned sa, const void* g) {
    asm volatile("cp.async.cg.shared.global [%0], [%1], 16;" :: "r"(sa), "l"(g));
}
__device__ __forceinline__ void cp16z(unsigned sa, const void* g, int srcsize) {
    asm volatile("cp.async.cg.shared.global [%0], [%1], 16, %2;"
                 :: "r"(sa), "l"(g), "r"(srcsize));
}
__device__ __forceinline__ void cp_commit() { asm volatile("cp.async.commit_group;"); }
__device__ __forceinline__ void cp_wait0()  { asm volatile("cp.async.wait_group 0;" ::: "memory"); }
__device__ __forceinline__ void cp_wait1()  { asm volatile("cp.async.wait_group 1;" ::: "memory"); }
__device__ __forceinline__ void cp_wait2()  { asm volatile("cp.async.wait_group 2;" ::: "memory"); }

__device__ __forceinline__ void ldsm4(unsigned addr, unsigned* r) {
    asm volatile("ldmatrix.sync.aligned.m8n8.x4.shared.b16 {%0,%1,%2,%3}, [%4];"
                 : "=r"(r[0]), "=r"(r[1]), "=r"(r[2]), "=r"(r[3]) : "r"(addr));
}
__device__ __forceinline__ void mma16816(float* c, const unsigned* a,
                                         unsigned b0, unsigned b1) {
    asm volatile(
        "mma.sync.aligned.m16n8k16.row.col.f32.bf16.bf16.f32 "
        "{%0,%1,%2,%3}, {%4,%5,%6,%7}, {%8,%9}, {%0,%1,%2,%3};"
        : "+f"(c[0]), "+f"(c[1]), "+f"(c[2]), "+f"(c[3])
        : "r"(a[0]), "r"(a[1]), "r"(a[2]), "r"(a[3]), "r"(b0), "r"(b1));
}

// ------------------------- power iteration ------------------------------------
__global__ void mv_T_kernel(const float* __restrict__ W, const float* __restrict__ vin,
                            float* __restrict__ vout) {
    int dl = threadIdx.x >> 5, lane = threadIdx.x & 31;
    int d = blockIdx.x * 8 + dl;
    float acc = 0.f;
    for (int e = lane; e < D_DIM; e += 32)
        acc += W[(size_t)e * D_DIM + d] * vin[e];
    #pragma unroll
    for (int off = 16; off; off >>= 1) acc += __shfl_down_sync(0xffffffffu, acc, off);
    if (lane == 0) vout[d] = acc;
}
__global__ void mv_N_kernel(const float* __restrict__ W, const float* __restrict__ vin,
                            float* __restrict__ vout) {
    int el = threadIdx.x >> 5, lane = threadIdx.x & 31;
    int e = blockIdx.x * 8 + el;
    float acc = 0.f;
    const float* row = W + (size_t)e * D_DIM;
    for (int d = lane; d < D_DIM; d += 32) acc += row[d] * vin[d];
    #pragma unroll
    for (int off = 16; off; off >>= 1) acc += __shfl_down_sync(0xffffffffu, acc, off);
    if (lane == 0) vout[e] = acc;
}
__global__ void finalize_kernel() {
    __shared__ float red[256];
    __shared__ float ssq[6];
    int tid = threadIdx.x;
    for (int v = 0; v < 6; v++) {
        float local = 0.f;
        for (int i = tid; i < D_DIM; i += 256) { float x = g_p[v][i]; local += x * x; }
        red[tid] = local;
        __syncthreads();
        for (int s = 128; s; s >>= 1) { if (tid < s) red[tid] += red[tid + s]; __syncthreads(); }
        if (tid == 0) ssq[v] = red[0];
        __syncthreads();
    }
    if (tid == 0) {
        float a1 = 1.f / (sqrtf(ssq[0]) + EPS_F);
        float b1 = a1 / (a1 * sqrtf(ssq[1]) + EPS_F);
        float a2 = b1 / (b1 * sqrtf(ssq[2]) + EPS_F);
        float b2 = a2 / (a2 * sqrtf(ssq[3]) + EPS_F);
        float a3 = b2 / (b2 * sqrtf(ssq[4]) + EPS_F);
        float b3 = a3 / (a3 * sqrtf(ssq[5]) + EPS_F);
        float sigma = fabsf(a3 * b3 * ssq[5]);
        g_scale = SPECTRAL_RADIUS / (sigma + EPS_F);
    }
}

// --------------------- split (+ transpose) kernel -----------------------------
__global__ void split_tr_kernel(const float* __restrict__ in, int useScale,
                                __nv_bfloat16* __restrict__ oh, __nv_bfloat16* __restrict__ ol,
                                __nv_bfloat16* __restrict__ oth, __nv_bfloat16* __restrict__ otl) {
    __shared__ float tile[32][33];
    float s = useScale ? g_scale : 1.0f;
    int bx = blockIdx.x, by = blockIdx.y;
    int tx = threadIdx.x, ty = threadIdx.y;     // 32 x 8
    #pragma unroll
    for (int k = 0; k < 4; k++) {
        int r = by * 32 + ty + k * 8, c = bx * 32 + tx;
        float v = in[(size_t)r * D_DIM + c] * s;
        tile[ty + k * 8][tx] = v;
        __nv_bfloat16 h = __float2bfloat16(v);
        oh[(size_t)r * D_DIM + c] = h;
        ol[(size_t)r * D_DIM + c] = __float2bfloat16(v - __bfloat162float(h));
    }
    __syncthreads();
    #pragma unroll
    for (int k = 0; k < 4; k++) {
        int rt = bx * 32 + ty + k * 8, ct = by * 32 + tx;
        float v = tile[tx][ty + k * 8];
        __nv_bfloat16 h = __float2bfloat16(v);
        oth[(size_t)rt * D_DIM + ct] = h;
        otl[(size_t)rt * D_DIM + ct] = __float2bfloat16(v - __bfloat162float(h));
    }
}

// ------------------------- prep for phase-1 j=0 -------------------------------
__global__ void prep1_kernel(const float* __restrict__ x, const float* __restrict__ h0,
                             __nv_bfloat16* __restrict__ ah, __nv_bfloat16* __restrict__ al) {
    size_t gid = (size_t)blockIdx.x * 256 + threadIdx.x;
    int m = (int)(gid >> 10), d = (int)(gid & 1023);
    int c = m >> 3, b = m & 7;
    int t = c * L_CH;
    float v = x[((size_t)t * B_DIM + b) * D_DIM + d];
    if (c == 0) v += h0[(size_t)b * D_DIM + d];
    __nv_bfloat16 h = __float2bfloat16(v);
    ah[gid] = h;
    al[gid] = __float2bfloat16(v - __bfloat162float(h));
}

// ------------------------- mma.sync split-bf16 GEMM ---------------------------
// R[m,n] = sum_k A[m+ashift,k]*B[n,k], A = Ah+Al, B = Bh+Bl (3-term split);
// rows with m+ashift < 0 are zero (cp.async zero-fill).
// Epilogue modes:
//  0: out[m,n] (+addsrc) ; optional split(v) -> sh/sl
//  1: phase1: v += bias; out_h[slot] = v; split(v + x[t+1]); optional fdst=S0
//  2: phase3: out_h[slot] += v; silu(h) -> fdst(out_silu); optional split(v)
__device__ __forceinline__ void load_chunk(unsigned smb, int stage,
        const __nv_bfloat16* Ah, const __nv_bfloat16* Al, int ashift,
        const __nv_bfloat16* Bh, const __nv_bfloat16* Bl,
        int arow0, int brow0, int kc, int tid) {
    unsigned sb = smb + stage * STAGE_BYTES;
    #pragma unroll
    for (int i = 0; i < 2; i++) {           // A: Ah,Al 64 rows x 4 x 16B
        int e = tid + i * 256;
        int arr = e >> 8;
        int rr = (e & 255) >> 2;
        int cc = e & 3;
        const __nv_bfloat16* src = arr ? Al : Ah;
        int r = arow0 + rr + ashift;
        int sz = (r >= 0) ? 16 : 0;
        if (r < 0) r = 0;
        cp16z(sb + arr * A_BYTES + rr * RB + cc * 16,
              src + (size_t)r * D_DIM + kc * KC + cc * 8, sz);
    }
    #pragma unroll
    for (int i = 0; i < 4; i++) {           // B: Bh,Bl 128 rows x 4 x 16B
        int e = tid + i * 256;
        int arr = e >> 9;
        int rr = (e & 511) >> 2;
        int cc = e & 3;
        const __nv_bfloat16* src = arr ? Bl : Bh;
        cp16(sb + 2 * A_BYTES + arr * B_BYTES + rr * RB + cc * 16,
             src + (size_t)(brow0 + rr) * D_DIM + kc * KC + cc * 8);
    }
    cp_commit();
}

__global__ void __launch_bounds__(256, 1)
gemm_kernel(const __nv_bfloat16* __restrict__ Ah, const __nv_bfloat16* __restrict__ Al,
            int ashift,
            const __nv_bfloat16* __restrict__ Bh, const __nv_bfloat16* __restrict__ Bl,
            float* __restrict__ out, const float* __restrict__ addsrc,
            const float* __restrict__ bias, const float* __restrict__ xnext,
            __nv_bfloat16* __restrict__ sh, __nv_bfloat16* __restrict__ sl,
            float* __restrict__ fdst, int emode, int jstep) {
    extern __shared__ char sm[];
    unsigned smb = smem_u32(sm);
    const int tid = threadIdx.x;
    const int wid = tid >> 5, lane = tid & 31;
    const int bx = blockIdx.x, by = blockIdx.y;
    const int warp_m = wid >> 2, warp_n = wid & 3;
    const int g = lane >> 2, tg = lane & 3;

    int arow0 = by * MT, brow0 = bx * NT;

    unsigned lrow = lane & 15, lhalf = lane >> 4;
    unsigned aBase = smb + (warp_m * 32 + lrow) * RB + lhalf * 16;
    unsigned bBase = smb + 2 * A_BYTES + (warp_n * 32 + lrow) * RB + lhalf * 16;

    float acc[2][4][4];
    #pragma unroll
    for (int i = 0; i < 2; i++)
        #pragma unroll
        for (int j = 0; j < 4; j++)
            #pragma unroll
            for (int q = 0; q < 4; q++) acc[i][j][q] = 0.f;

    const int NKC = D_DIM / KC;   // 32
    // prologue: 3 chunks in flight
    #pragma unroll
    for (int s = 0; s < NSTAGE - 1; s++)
        load_chunk(smb, s, Ah, Al, ashift, Bh, Bl, arow0, brow0, s, tid);

    for (int kc = 0; kc < NKC; kc++) {
        int st = kc & (NSTAGE - 1);
        int remain = NKC - 1 - kc;
        if (remain >= 2) cp_wait2();
        else if (remain == 1) cp_wait1();
        else cp_wait0();
        __syncthreads();
        if (kc + NSTAGE - 1 < NKC)
            load_chunk(smb, (kc + NSTAGE - 1) & (NSTAGE - 1),
                       Ah, Al, ashift, Bh, Bl, arow0, brow0, kc + NSTAGE - 1, tid);

        unsigned sa = aBase + st * STAGE_BYTES;
        unsigned sb = bBase + st * STAGE_BYTES;
        #pragma unroll
        for (int ks = 0; ks < 2; ks++) {
            unsigned ko = ks * 32;
            unsigned AH0[4], AH1[4], AL0[4], AL1[4];
            ldsm4(sa + ko, AH0);
            ldsm4(sa + 16 * RB + ko, AH1);
            ldsm4(sa + A_BYTES + ko, AL0);
            ldsm4(sa + A_BYTES + 16 * RB + ko, AL1);
            unsigned BH0[4], BH1[4], BL0[4], BL1[4];
            ldsm4(sb + ko, BH0);
            ldsm4(sb + 16 * RB + ko, BH1);
            ldsm4(sb + B_BYTES + ko, BL0);
            ldsm4(sb + B_BYTES + 16 * RB + ko, BL1);

            unsigned bh[4][2] = {{BH0[0],BH0[2]},{BH0[1],BH0[3]},
                                 {BH1[0],BH1[2]},{BH1[1],BH1[3]}};
            unsigned bl[4][2] = {{BL0[0],BL0[2]},{BL0[1],BL0[3]},
                                 {BL1[0],BL1[2]},{BL1[1],BL1[3]}};
            #pragma unroll
            for (int j = 0; j < 4; j++) {
                mma16816(acc[0][j], AH0, bh[j][0], bh[j][1]);
                mma16816(acc[0][j], AH0, bl[j][0], bl[j][1]);
                mma16816(acc[0][j], AL0, bh[j][0], bh[j][1]);
                mma16816(acc[1][j], AH1, bh[j][0], bh[j][1]);
                mma16816(acc[1][j], AH1, bl[j][0], bl[j][1]);
                mma16816(acc[1][j], AL1, bh[j][0], bh[j][1]);
            }
        }
    }

    // Epilogue
    #pragma unroll
    for (int i = 0; i < 2; i++) {
        #pragma unroll
        for (int j = 0; j < 4; j++) {
            int rm = by * MT + warp_m * 32 + i * 16 + g;
            int col = bx * NT + warp_n * 32 + j * 8 + tg * 2;
            #pragma unroll
            for (int half = 0; half < 2; half++) {
                int r = rm + half * 8;
                float vx = acc[i][j][half * 2 + 0];
                float vy = acc[i][j][half * 2 + 1];
                size_t flat = (size_t)r * D_DIM + col;
                if (emode == 0) {
                    if (addsrc) {
                        float2 a2 = *(const float2*)(addsrc + flat);
                        vx += a2.x; vy += a2.y;
                    }
                    float2 o; o.x = vx; o.y = vy;
                    *(float2*)(out + flat) = o;
                    if (sh) {
                        __nv_bfloat16 hx = __float2bfloat16(vx);
                        __nv_bfloat16 hy = __float2bfloat16(vy);
                        __nv_bfloat162 h2; h2.x = hx; h2.y = hy;
                        __nv_bfloat162 l2;
                        l2.x = __float2bfloat16(vx - __bfloat162float(hx));
                        l2.y = __float2bfloat16(vy - __bfloat162float(hy));
                        *(__nv_bfloat162*)(sh + flat) = h2;
                        *(__nv_bfloat162*)(sl + flat) = l2;
                    }
                } else {
                    int c = r >> 3, b = r & 7;
                    int t1 = c * L_CH + jstep + 1;
                    size_t idx = ((size_t)t1 * B_DIM + b) * D_DIM + col;
                    if (emode == 1) {
                        float2 b2 = *(const float2*)(bias + col);
                        vx += b2.x; vy += b2.y;
                        float2 o; o.x = vx; o.y = vy;
                        *(float2*)(out + idx) = o;
                        if (fdst) { float2 f; f.x = vx; f.y = vy;
                                    *(float2*)(fdst + flat) = f; }
                        float sx = vx, sy = vy;
                        if (xnext) {
                            float2 xv = *(const float2*)(xnext + idx);
                            sx += xv.x; sy += xv.y;
                        }
                        __nv_bfloat16 hx = __float2bfloat16(sx);
                        __nv_bfloat16 hy = __float2bfloat16(sy);
                        __nv_bfloat162 h2; h2.x = hx; h2.y = hy;
                        __nv_bfloat162 l2;
                        l2.x = __float2bfloat16(sx - __bfloat162float(hx));
                        l2.y = __float2bfloat16(sy - __bfloat162float(hy));
                        *(__nv_bfloat162*)(sh + flat) = h2;
                        *(__nv_bfloat162*)(sl + flat) = l2;
                    } else {  // emode == 2: accumulate + fused silu
                        float2 o = *(const float2*)(out + idx);
                        o.x += vx; o.y += vy;
                        *(float2*)(out + idx) = o;
                        // silu of final h -> output[t1-1] (= idx - B*D)
                        float2 sv;
                        sv.x = o.x / (1.f + expf(-o.x));
                        sv.y = o.y / (1.f + expf(-o.y));
                        *(float2*)(fdst + idx - (size_t)B_DIM * D_DIM) = sv;
                        if (sh) {
                            __nv_bfloat16 hx = __float2bfloat16(vx);
                            __nv_bfloat16 hy = __float2bfloat16(vy);
                            __nv_bfloat162 h2; h2.x = hx; h2.y = hy;
                            __nv_bfloat162 l2;
                            l2.x = __float2bfloat16(vx - __bfloat162float(hx));
                            l2.y = __float2bfloat16(vy - __bfloat162float(hy));
                            *(__nv_bfloat162*)(sh + flat) = h2;
                            *(__nv_bfloat162*)(sl + flat) = l2;
                        }
                    }
                }
            }
        }
    }
}

// ------------------------------- launcher ------------------------------------
extern "C" void kernel_launch(void* const* d_in, const int* in_sizes, int n_in,
                              void* d_out, int out_size) {
    const float* x  = (const float*)d_in[0];
    const float* h0 = (const float*)d_in[1];
    const float* W  = (const float*)d_in[2];
    const float* bv = (const float*)d_in[3];
    const float* u  = (const float*)d_in[4];

    float* out_silu = (float*)d_out;
    float* out_h    = (float*)d_out + (size_t)T_DIM * B_DIM * D_DIM;  // h[0..T]

    float *p, *pow_, *S0, *S1;
    __nv_bfloat16 *Wh, *Wl, *WTh, *WTl, *Ph, *Pl, *PTh, *PTl;
    __nv_bfloat16 *p0h, *p0l, *p1h, *p1l;
    cudaGetSymbolAddress((void**)&p, g_p);
    cudaGetSymbolAddress((void**)&pow_, g_pow);
    cudaGetSymbolAddress((void**)&S0, g_S);   S1 = S0 + DD;
    cudaGetSymbolAddress((void**)&Wh, g_Wh);   cudaGetSymbolAddress((void**)&Wl, g_Wl);
    cudaGetSymbolAddress((void**)&WTh, g_WTh); cudaGetSymbolAddress((void**)&WTl, g_WTl);
    cudaGetSymbolAddress((void**)&Ph, g_Ph);   cudaGetSymbolAddress((void**)&Pl, g_Pl);
    cudaGetSymbolAddress((void**)&PTh, g_PTh); cudaGetSymbolAddress((void**)&PTl, g_PTl);
    cudaGetSymbolAddress((void**)&p0h, g_Ah);  cudaGetSymbolAddress((void**)&p0l, g_Al);
    cudaGetSymbolAddress((void**)&p1h, g_Ch);  cudaGetSymbolAddress((void**)&p1l, g_Cl);

    cudaFuncSetAttribute(gemm_kernel, cudaFuncAttributeMaxDynamicSharedMemorySize,
                         GEMM_SMEM);

    __nv_bfloat16* pairh[2] = {p0h, p1h};
    __nv_bfloat16* pairl[2] = {p0l, p1l};

    // h[0] = h0
    cudaMemcpyAsync(out_h, h0, sizeof(float) * B_DIM * D_DIM, cudaMemcpyDeviceToDevice, 0);

    // ---- spectral scale ----
    mv_T_kernel<<<128, 256>>>(W, u, p + 0 * D_DIM);
    mv_N_kernel<<<128, 256>>>(W, p + 0 * D_DIM, p + 1 * D_DIM);
    mv_T_kernel<<<128, 256>>>(W, p + 1 * D_DIM, p + 2 * D_DIM);
    mv_N_kernel<<<128, 256>>>(W, p + 2 * D_DIM, p + 3 * D_DIM);
    mv_T_kernel<<<128, 256>>>(W, p + 3 * D_DIM, p + 4 * D_DIM);
    mv_N_kernel<<<128, 256>>>(W, p + 4 * D_DIM, p + 5 * D_DIM);
    finalize_kernel<<<1, 256>>>();

    dim3 trg(32, 32), trb(32, 8);
    dim3 gg(D_DIM / NT, D_DIM / MT);   // (8, 16)
    split_tr_kernel<<<trg, trb>>>(W, 1, Wh, Wl, WTh, WTl);

    // ---- phase 1: 8 GEMMs; epilogue writes h slot + split(h + x_next) --------
    prep1_kernel<<<4096, 256>>>(x, h0, p0h, p0l);
    for (int j = 0; j < L_CH; j++) {
        int in = j & 1, outp = (j + 1) & 1;
        gemm_kernel<<<gg, 256, GEMM_SMEM>>>(
            pairh[in], pairl[in], 0, Wh, Wl, out_h, nullptr, bv,
            (j < 7) ? x : nullptr, pairh[outp], pairl[outp],
            (j == 7) ? S0 : nullptr, 1, j);
    }

    // ---- squarings to A^8 ----
    gemm_kernel<<<gg, 256, GEMM_SMEM>>>(Wh, Wl, 0, WTh, WTl, pow_, nullptr, nullptr,
                                        nullptr, nullptr, nullptr, nullptr, 0, 0);
    split_tr_kernel<<<trg, trb>>>(pow_, 0, Ph, Pl, PTh, PTl);
    gemm_kernel<<<gg, 256, GEMM_SMEM>>>(Ph, Pl, 0, PTh, PTl, pow_, nullptr, nullptr,
                                        nullptr, nullptr, nullptr, nullptr, 0, 0);
    split_tr_kernel<<<trg, trb>>>(pow_, 0, Ph, Pl, PTh, PTl);
    gemm_kernel<<<gg, 256, GEMM_SMEM>>>(Ph, Pl, 0, PTh, PTl, pow_, nullptr, nullptr,
                                        nullptr, nullptr, nullptr, nullptr, 0, 0);
    split_tr_kernel<<<trg, trb>>>(pow_, 0, Ph, Pl, PTh, PTl);

    // ---- boundary doubling scan: 7 rounds; shift folded into A-loads ---------
    float* Sc = S0;
    float* Sn = S1;
    for (int r = 0; r < 7; r++) {
        int in = r & 1, outp = (r + 1) & 1;
        gemm_kernel<<<gg, 256, GEMM_SMEM>>>(
            pairh[in], pairl[in], -(1 << r) * B_DIM, Ph, Pl, Sn, Sc, nullptr,
            nullptr, pairh[outp], pairl[outp], nullptr, 0, 0);
        float* tmp = Sc; Sc = Sn; Sn = tmp;
        if (r < 6) {
            gemm_kernel<<<gg, 256, GEMM_SMEM>>>(Ph, Pl, 0, PTh, PTl, pow_, nullptr,
                                                nullptr, nullptr, nullptr, nullptr,
                                                nullptr, 0, 0);
            split_tr_kernel<<<trg, trb>>>(pow_, 0, Ph, Pl, PTh, PTl);
        }
    }

    // ---- phase 3: fixup; epilogue accumulates into h slots + fused silu ------
    for (int j = 0; j < L_CH; j++) {
        int in = (j + 1) & 1, outp = j & 1;
        gemm_kernel<<<gg, 256, GEMM_SMEM>>>(
            pairh[in], pairl[in], (j == 0) ? -B_DIM : 0, Wh, Wl, out_h, nullptr,
            nullptr, nullptr, (j < 7) ? pairh[outp] : nullptr,
            (j < 7) ? pairl[outp] : nullptr, out_silu, 2, j);
    }
}

// round 14
// speedup vs baseline: 1.1803x; 1.1800x over previous
#include <cuda_runtime.h>
#include <cuda_fp16.h>
#include <cstdint>
#include <stdint.h>
#include <math.h>

#define D_DIM 1024
#define B_DIM 8
#define T_DIM 1024
#define L_CH 8
#define DD (1024*1024)
#define SPECTRAL_RADIUS 0.999f
#define EPS_F 1e-8f

// GEMM tiling: CTA tile 64(M) x 128(N), K-chunk 32, 4-stage pipeline.
#define MT 64
#define NT 128
#define KC 32
#define RB 80                               // smem row bytes (40 fp16, pad 8)
#define A_BYTES (MT * RB)                   // 5120
#define B_BYTES (NT * RB)                   // 10240
#define STAGE_BYTES (2 * A_BYTES + 2 * B_BYTES)  // 30720
#define NSTAGE 4
#define GEMM_SMEM (NSTAGE * STAGE_BYTES)    // 122880

// ------------------------- device scratch ------------------------------------
__device__ float g_p[6][D_DIM];
__device__ float g_scale;
__device__ __align__(256) __half g_Wh[DD], g_Wl[DD], g_WTh[DD], g_WTl[DD];
__device__ __align__(256) __half g_Ph[DD], g_Pl[DD], g_PTh[DD], g_PTl[DD];
__device__ __align__(256) __half g_X0[DD], g_X1[DD];          // state ping-pong
__device__ __align__(256) float g_pow[DD], g_S[2][DD];

// ------------------------- PTX helpers ---------------------------------------
__device__ __forceinline__ unsigned smem_u32(const void* p) {
    unsigned a;
    asm("{ .reg .u64 t; cvta.to.shared.u64 t, %1; cvt.u32.u64 %0, t; }" : "=r"(a) : "l"(p));
    return a;
}
__device__ __forceinline__ void cp16(unsigned sa, const void* g) {
    asm volatile("cp.async.cg.shared.global [%0], [%1], 16;" :: "r"(sa), "l"(g));
}
__device__ __forceinline__ void cp16z(unsigned sa, const void* g, int srcsize) {
    asm volatile("cp.async.cg.shared.global [%0], [%1], 16, %2;"
                 :: "r"(sa), "l"(g), "r"(srcsize));
}
__device__ __forceinline__ void cp_commit() { asm volatile("cp.async.commit_group;"); }
__device__ __forceinline__ void cp_wait0()  { asm volatile("cp.async.wait_group 0;" ::: "memory"); }
__device__ __forceinline__ void cp_wait1()  { asm volatile("cp.async.wait_group 1;" ::: "memory"); }
__device__ __forceinline__ void cp_wait2()  { asm volatile("cp.async.wait_group 2;" ::: "memory"); }

__device__ __forceinline__ void ldsm4(unsigned addr, unsigned* r) {
    asm volatile("ldmatrix.sync.aligned.m8n8.x4.shared.b16 {%0,%1,%2,%3}, [%4];"
                 : "=r"(r[0]), "=r"(r[1]), "=r"(r[2]), "=r"(r[3]) : "r"(addr));
}
__device__ __forceinline__ void mma16816(float* c, const unsigned* a,
                                         unsigned b0, unsigned b1) {
    asm volatile(
        "mma.sync.aligned.m16n8k16.row.col.f32.f16.f16.f32 "
        "{%0,%1,%2,%3}, {%4,%5,%6,%7}, {%8,%9}, {%0,%1,%2,%3};"
        : "+f"(c[0]), "+f"(c[1]), "+f"(c[2]), "+f"(c[3])
        : "r"(a[0]), "r"(a[1]), "r"(a[2]), "r"(a[3]), "r"(b0), "r"(b1));
}

// ------------------------- power iteration ------------------------------------
__global__ void mv_T_kernel(const float* __restrict__ W, const float* __restrict__ vin,
                            float* __restrict__ vout) {
    int dl = threadIdx.x >> 5, lane = threadIdx.x & 31;
    int d = blockIdx.x * 8 + dl;
    float acc = 0.f;
    for (int e = lane; e < D_DIM; e += 32)
        acc += W[(size_t)e * D_DIM + d] * vin[e];
    #pragma unroll
    for (int off = 16; off; off >>= 1) acc += __shfl_down_sync(0xffffffffu, acc, off);
    if (lane == 0) vout[d] = acc;
}
__global__ void mv_N_kernel(const float* __restrict__ W, const float* __restrict__ vin,
                            float* __restrict__ vout) {
    int el = threadIdx.x >> 5, lane = threadIdx.x & 31;
    int e = blockIdx.x * 8 + el;
    float acc = 0.f;
    const float* row = W + (size_t)e * D_DIM;
    for (int d = lane; d < D_DIM; d += 32) acc += row[d] * vin[d];
    #pragma unroll
    for (int off = 16; off; off >>= 1) acc += __shfl_down_sync(0xffffffffu, acc, off);
    if (lane == 0) vout[e] = acc;
}
__global__ void finalize_kernel() {
    __shared__ float red[256];
    __shared__ float ssq[6];
    int tid = threadIdx.x;
    for (int v = 0; v < 6; v++) {
        float local = 0.f;
        for (int i = tid; i < D_DIM; i += 256) { float x = g_p[v][i]; local += x * x; }
        red[tid] = local;
        __syncthreads();
        for (int s = 128; s; s >>= 1) { if (tid < s) red[tid] += red[tid + s]; __syncthreads(); }
        if (tid == 0) ssq[v] = red[0];
        __syncthreads();
    }
    if (tid == 0) {
        float a1 = 1.f / (sqrtf(ssq[0]) + EPS_F);
        float b1 = a1 / (a1 * sqrtf(ssq[1]) + EPS_F);
        float a2 = b1 / (b1 * sqrtf(ssq[2]) + EPS_F);
        float b2 = a2 / (a2 * sqrtf(ssq[3]) + EPS_F);
        float a3 = b2 / (b2 * sqrtf(ssq[4]) + EPS_F);
        float b3 = a3 / (a3 * sqrtf(ssq[5]) + EPS_F);
        float sigma = fabsf(a3 * b3 * ssq[5]);
        g_scale = SPECTRAL_RADIUS / (sigma + EPS_F);
    }
}

// --------------------- split (+ transpose) kernel (fp16) ----------------------
__global__ void split_tr_kernel(const float* __restrict__ in, int useScale,
                                __half* __restrict__ oh, __half* __restrict__ ol,
                                __half* __restrict__ oth, __half* __restrict__ otl) {
    __shared__ float tile[32][33];
    float s = useScale ? g_scale : 1.0f;
    int bx = blockIdx.x, by = blockIdx.y;
    int tx = threadIdx.x, ty = threadIdx.y;     // 32 x 8
    #pragma unroll
    for (int k = 0; k < 4; k++) {
        int r = by * 32 + ty + k * 8, c = bx * 32 + tx;
        float v = in[(size_t)r * D_DIM + c] * s;
        tile[ty + k * 8][tx] = v;
        __half h = __float2half(v);
        oh[(size_t)r * D_DIM + c] = h;
        ol[(size_t)r * D_DIM + c] = __float2half(v - __half2float(h));
    }
    __syncthreads();
    #pragma unroll
    for (int k = 0; k < 4; k++) {
        int rt = bx * 32 + ty + k * 8, ct = by * 32 + tx;
        float v = tile[tx][ty + k * 8];
        __half h = __float2half(v);
        oth[(size_t)rt * D_DIM + ct] = h;
        otl[(size_t)rt * D_DIM + ct] = __float2half(v - __half2float(h));
    }
}

// ------------------------- prep for phase-1 j=0 -------------------------------
__global__ void prep1_kernel(const float* __restrict__ x, const float* __restrict__ h0,
                             __half* __restrict__ a) {
    size_t gid = (size_t)blockIdx.x * 256 + threadIdx.x;
    int m = (int)(gid >> 10), d = (int)(gid & 1023);
    int c = m >> 3, b = m & 7;
    int t = c * L_CH;
    float v = x[((size_t)t * B_DIM + b) * D_DIM + d];
    if (c == 0) v += h0[(size_t)b * D_DIM + d];
    a[gid] = __float2half(v);
}

// ------------------------- mma.sync fp16 GEMM ---------------------------------
// R[m,n] = sum_k A[m+ashift,k]*B[n,k].  B = Bh + Bl (always split).
// HASAL=1: A = Ah + Al (3 products, for matrix squarings).
// HASAL=0: A = Ah single fp16 (2 products, for activation/state chains).
// Rows with m+ashift < 0 are zero (cp.async zero-fill).
// Epilogue modes:
//  0: out[m,n] (+addsrc) ; optional half(v) -> sh
//  1: phase1: v += bias; out_h[slot] = v; sh = half(v + x[t+1]); optional fdst=S0
//  2: phase3: out_h[slot] += v; silu(h) -> fdst(out_silu); optional sh = half(v)
template<int HASAL>
__device__ __forceinline__ void load_chunk(unsigned smb, int stage,
        const __half* Ah, const __half* Al, int ashift,
        const __half* Bh, const __half* Bl,
        int arow0, int brow0, int kc, int tid) {
    unsigned sb = smb + stage * STAGE_BYTES;
    #pragma unroll
    for (int i = 0; i < (HASAL ? 2 : 1); i++) {   // A arrays: 64 rows x 4 x 16B
        int e = tid + i * 256;
        int arr = e >> 8;
        int rr = (e & 255) >> 2;
        int cc = e & 3;
        const __half* src = arr ? Al : Ah;
        int r = arow0 + rr + ashift;
        int sz = (r >= 0) ? 16 : 0;
        if (r < 0) r = 0;
        cp16z(sb + arr * A_BYTES + rr * RB + cc * 16,
              src + (size_t)r * D_DIM + kc * KC + cc * 8, sz);
    }
    #pragma unroll
    for (int i = 0; i < 4; i++) {           // B: Bh,Bl 128 rows x 4 x 16B
        int e = tid + i * 256;
        int arr = e >> 9;
        int rr = (e & 511) >> 2;
        int cc = e & 3;
        const __half* src = arr ? Bl : Bh;
        cp16(sb + 2 * A_BYTES + arr * B_BYTES + rr * RB + cc * 16,
             src + (size_t)(brow0 + rr) * D_DIM + kc * KC + cc * 8);
    }
    cp_commit();
}

template<int HASAL>
__global__ void __launch_bounds__(256, 1)
gemm_kernel(const __half* __restrict__ Ah, const __half* __restrict__ Al,
            int ashift,
            const __half* __restrict__ Bh, const __half* __restrict__ Bl,
            float* __restrict__ out, const float* __restrict__ addsrc,
            const float* __restrict__ bias, const float* __restrict__ xnext,
            __half* __restrict__ sh, float* __restrict__ fdst,
            int emode, int jstep) {
    extern __shared__ char sm[];
    unsigned smb = smem_u32(sm);
    const int tid = threadIdx.x;
    const int wid = tid >> 5, lane = tid & 31;
    const int bx = blockIdx.x, by = blockIdx.y;
    const int warp_m = wid >> 2, warp_n = wid & 3;
    const int g = lane >> 2, tg = lane & 3;

    int arow0 = by * MT, brow0 = bx * NT;

    unsigned lrow = lane & 15, lhalf = lane >> 4;
    unsigned aBase = smb + (warp_m * 32 + lrow) * RB + lhalf * 16;
    unsigned bBase = smb + 2 * A_BYTES + (warp_n * 32 + lrow) * RB + lhalf * 16;

    float acc[2][4][4];
    #pragma unroll
    for (int i = 0; i < 2; i++)
        #pragma unroll
        for (int j = 0; j < 4; j++)
            #pragma unroll
            for (int q = 0; q < 4; q++) acc[i][j][q] = 0.f;

    const int NKC = D_DIM / KC;   // 32
    #pragma unroll
    for (int s = 0; s < NSTAGE - 1; s++)
        load_chunk<HASAL>(smb, s, Ah, Al, ashift, Bh, Bl, arow0, brow0, s, tid);

    for (int kc = 0; kc < NKC; kc++) {
        int st = kc & (NSTAGE - 1);
        int remain = NKC - 1 - kc;
        if (remain >= 2) cp_wait2();
        else if (remain == 1) cp_wait1();
        else cp_wait0();
        __syncthreads();
        if (kc + NSTAGE - 1 < NKC)
            load_chunk<HASAL>(smb, (kc + NSTAGE - 1) & (NSTAGE - 1),
                              Ah, Al, ashift, Bh, Bl, arow0, brow0,
                              kc + NSTAGE - 1, tid);

        unsigned sa = aBase + st * STAGE_BYTES;
        unsigned sb = bBase + st * STAGE_BYTES;
        #pragma unroll
        for (int ks = 0; ks < 2; ks++) {
            unsigned ko = ks * 32;
            unsigned AH0[4], AH1[4];
            ldsm4(sa + ko, AH0);
            ldsm4(sa + 16 * RB + ko, AH1);
            unsigned AL0[4], AL1[4];
            if (HASAL) {
                ldsm4(sa + A_BYTES + ko, AL0);
                ldsm4(sa + A_BYTES + 16 * RB + ko, AL1);
            }
            unsigned BH0[4], BH1[4], BL0[4], BL1[4];
            ldsm4(sb + ko, BH0);
            ldsm4(sb + 16 * RB + ko, BH1);
            ldsm4(sb + B_BYTES + ko, BL0);
            ldsm4(sb + B_BYTES + 16 * RB + ko, BL1);

            unsigned bh[4][2] = {{BH0[0],BH0[2]},{BH0[1],BH0[3]},
                                 {BH1[0],BH1[2]},{BH1[1],BH1[3]}};
            unsigned bl[4][2] = {{BL0[0],BL0[2]},{BL0[1],BL0[3]},
                                 {BL1[0],BL1[2]},{BL1[1],BL1[3]}};
            #pragma unroll
            for (int j = 0; j < 4; j++) {
                mma16816(acc[0][j], AH0, bh[j][0], bh[j][1]);
                mma16816(acc[0][j], AH0, bl[j][0], bl[j][1]);
                if (HASAL) mma16816(acc[0][j], AL0, bh[j][0], bh[j][1]);
                mma16816(acc[1][j], AH1, bh[j][0], bh[j][1]);
                mma16816(acc[1][j], AH1, bl[j][0], bl[j][1]);
                if (HASAL) mma16816(acc[1][j], AL1, bh[j][0], bh[j][1]);
            }
        }
    }

    // Epilogue
    #pragma unroll
    for (int i = 0; i < 2; i++) {
        #pragma unroll
        for (int j = 0; j < 4; j++) {
            int rm = by * MT + warp_m * 32 + i * 16 + g;
            int col = bx * NT + warp_n * 32 + j * 8 + tg * 2;
            #pragma unroll
            for (int half = 0; half < 2; half++) {
                int r = rm + half * 8;
                float vx = acc[i][j][half * 2 + 0];
                float vy = acc[i][j][half * 2 + 1];
                size_t flat = (size_t)r * D_DIM + col;
                if (emode == 0) {
                    if (addsrc) {
                        float2 a2 = *(const float2*)(addsrc + flat);
                        vx += a2.x; vy += a2.y;
                    }
                    float2 o; o.x = vx; o.y = vy;
                    *(float2*)(out + flat) = o;
                    if (sh)
                        *(__half2*)(sh + flat) = __floats2half2_rn(vx, vy);
                } else {
                    int c = r >> 3, b = r & 7;
                    int t1 = c * L_CH + jstep + 1;
                    size_t idx = ((size_t)t1 * B_DIM + b) * D_DIM + col;
                    if (emode == 1) {
                        float2 b2 = *(const float2*)(bias + col);
                        vx += b2.x; vy += b2.y;
                        float2 o; o.x = vx; o.y = vy;
                        *(float2*)(out + idx) = o;
                        if (fdst) { float2 f; f.x = vx; f.y = vy;
                                    *(float2*)(fdst + flat) = f; }
                        float sx = vx, sy = vy;
                        if (xnext) {
                            float2 xv = *(const float2*)(xnext + idx);
                            sx += xv.x; sy += xv.y;
                        }
                        *(__half2*)(sh + flat) = __floats2half2_rn(sx, sy);
                    } else {  // emode == 2: accumulate + fused silu
                        float2 o = *(const float2*)(out + idx);
                        o.x += vx; o.y += vy;
                        *(float2*)(out + idx) = o;
                        float2 sv;
                        sv.x = o.x / (1.f + expf(-o.x));
                        sv.y = o.y / (1.f + expf(-o.y));
                        *(float2*)(fdst + idx - (size_t)B_DIM * D_DIM) = sv;
                        if (sh)
                            *(__half2*)(sh + flat) = __floats2half2_rn(vx, vy);
                    }
                }
            }
        }
    }
}

// ------------------------------- launcher ------------------------------------
extern "C" void kernel_launch(void* const* d_in, const int* in_sizes, int n_in,
                              void* d_out, int out_size) {
    const float* x  = (const float*)d_in[0];
    const float* h0 = (const float*)d_in[1];
    const float* W  = (const float*)d_in[2];
    const float* bv = (const float*)d_in[3];
    const float* u  = (const float*)d_in[4];

    float* out_silu = (float*)d_out;
    float* out_h    = (float*)d_out + (size_t)T_DIM * B_DIM * D_DIM;  // h[0..T]

    float *p, *pow_, *S0, *S1;
    __half *Wh, *Wl, *WTh, *WTl, *Ph, *Pl, *PTh, *PTl, *X0, *X1;
    cudaGetSymbolAddress((void**)&p, g_p);
    cudaGetSymbolAddress((void**)&pow_, g_pow);
    cudaGetSymbolAddress((void**)&S0, g_S);   S1 = S0 + DD;
    cudaGetSymbolAddress((void**)&Wh, g_Wh);   cudaGetSymbolAddress((void**)&Wl, g_Wl);
    cudaGetSymbolAddress((void**)&WTh, g_WTh); cudaGetSymbolAddress((void**)&WTl, g_WTl);
    cudaGetSymbolAddress((void**)&Ph, g_Ph);   cudaGetSymbolAddress((void**)&Pl, g_Pl);
    cudaGetSymbolAddress((void**)&PTh, g_PTh); cudaGetSymbolAddress((void**)&PTl, g_PTl);
    cudaGetSymbolAddress((void**)&X0, g_X0);   cudaGetSymbolAddress((void**)&X1, g_X1);

    cudaFuncSetAttribute(gemm_kernel<0>, cudaFuncAttributeMaxDynamicSharedMemorySize,
                         GEMM_SMEM);
    cudaFuncSetAttribute(gemm_kernel<1>, cudaFuncAttributeMaxDynamicSharedMemorySize,
                         GEMM_SMEM);

    __half* st[2] = {X0, X1};

    // h[0] = h0
    cudaMemcpyAsync(out_h, h0, sizeof(float) * B_DIM * D_DIM, cudaMemcpyDeviceToDevice, 0);

    // ---- spectral scale ----
    mv_T_kernel<<<128, 256>>>(W, u, p + 0 * D_DIM);
    mv_N_kernel<<<128, 256>>>(W, p + 0 * D_DIM, p + 1 * D_DIM);
    mv_T_kernel<<<128, 256>>>(W, p + 1 * D_DIM, p + 2 * D_DIM);
    mv_N_kernel<<<128, 256>>>(W, p + 2 * D_DIM, p + 3 * D_DIM);
    mv_T_kernel<<<128, 256>>>(W, p + 3 * D_DIM, p + 4 * D_DIM);
    mv_N_kernel<<<128, 256>>>(W, p + 4 * D_DIM, p + 5 * D_DIM);
    finalize_kernel<<<1, 256>>>();

    dim3 trg(32, 32), trb(32, 8);
    dim3 gg(D_DIM / NT, D_DIM / MT);   // (8, 16)
    split_tr_kernel<<<trg, trb>>>(W, 1, Wh, Wl, WTh, WTl);

    // ---- phase 1: 8 GEMMs (2-product); epilogue: h slot + half(h + x_next) ---
    prep1_kernel<<<4096, 256>>>(x, h0, X0);
    for (int j = 0; j < L_CH; j++) {
        int in = j & 1, outp = (j + 1) & 1;
        gemm_kernel<0><<<gg, 256, GEMM_SMEM>>>(
            st[in], nullptr, 0, Wh, Wl, out_h, nullptr, bv,
            (j < 7) ? x : nullptr, st[outp], (j == 7) ? S0 : nullptr, 1, j);
    }

    // ---- squarings to A^8 (3-product, both operands split) ----
    gemm_kernel<1><<<gg, 256, GEMM_SMEM>>>(Wh, Wl, 0, WTh, WTl, pow_, nullptr,
                                           nullptr, nullptr, nullptr, nullptr, 0, 0);
    split_tr_kernel<<<trg, trb>>>(pow_, 0, Ph, Pl, PTh, PTl);
    gemm_kernel<1><<<gg, 256, GEMM_SMEM>>>(Ph, Pl, 0, PTh, PTl, pow_, nullptr,
                                           nullptr, nullptr, nullptr, nullptr, 0, 0);
    split_tr_kernel<<<trg, trb>>>(pow_, 0, Ph, Pl, PTh, PTl);
    gemm_kernel<1><<<gg, 256, GEMM_SMEM>>>(Ph, Pl, 0, PTh, PTl, pow_, nullptr,
                                           nullptr, nullptr, nullptr, nullptr, 0, 0);
    split_tr_kernel<<<trg, trb>>>(pow_, 0, Ph, Pl, PTh, PTl);

    // ---- boundary doubling scan: 7 rounds (2-product states) -----------------
    float* Sc = S0;
    float* Sn = S1;
    for (int r = 0; r < 7; r++) {
        int in = r & 1, outp = (r + 1) & 1;
        gemm_kernel<0><<<gg, 256, GEMM_SMEM>>>(
            st[in], nullptr, -(1 << r) * B_DIM, Ph, Pl, Sn, Sc, nullptr,
            nullptr, st[outp], nullptr, 0, 0);
        float* tmp = Sc; Sc = Sn; Sn = tmp;
        if (r < 6) {
            gemm_kernel<1><<<gg, 256, GEMM_SMEM>>>(Ph, Pl, 0, PTh, PTl, pow_,
                                                   nullptr, nullptr, nullptr,
                                                   nullptr, nullptr, 0, 0);
            split_tr_kernel<<<trg, trb>>>(pow_, 0, Ph, Pl, PTh, PTl);
        }
    }

    // ---- phase 3: fixup (2-product); accumulate into h slots + fused silu ----
    for (int j = 0; j < L_CH; j++) {
        int in = (j + 1) & 1, outp = j & 1;
        gemm_kernel<0><<<gg, 256, GEMM_SMEM>>>(
            st[in], nullptr, (j == 0) ? -B_DIM : 0, Wh, Wl, out_h, nullptr,
            nullptr, nullptr, (j < 7) ? st[outp] : nullptr, out_silu, 2, j);
    }
}